// round 15
// baseline (speedup 1.0000x reference)
#include <cuda_runtime.h>
#include <cuda_bf16.h>
#include <stdint.h>

#define NB 4
#define NN 3600
#define NC 16
#define NW 128          /* padded adjacency words per row (113 used) */
#define NWU 113         /* ceil(3600/32) */
#define NPAD 3616       /* boxes padded: 113 tiles * 32 */
#define NT 113          /* 32-wide tiles per dimension */
#define NTRI 6441       /* NT*(NT+1)/2 upper-tri tiles */
#define K1_SMEM (NPAD * 16 + NPAD * 4)
#define NXB 111         /* x-blocks in k_adj */
#define K1_THR 384      /* 12 warps */

typedef unsigned long long ull;

// ---------------------------------------------------------------------------
// Scratch (device globals; no allocation)
// ---------------------------------------------------------------------------
__device__ unsigned int g_adj[NB][NN][NW];     // adjacency bitmask (7.4 MB)
__device__ unsigned int g_val[NB][NC][NW];     // valid0 bitmask per (b,c)

__device__ __forceinline__ unsigned bit_transpose32(unsigned x, int lane) {
#pragma unroll
    for (int s = 16; s > 0; s >>= 1) {
        unsigned mask = (s == 16) ? 0x0000FFFFu : (s == 8) ? 0x00FF00FFu
                      : (s == 4) ? 0x0F0F0F0Fu : (s == 2) ? 0x33333333u
                      : 0x55555555u;
        unsigned y = __shfl_xor_sync(0xffffffffu, x, s);
        x = (lane & s) ? ((x & ~mask) | ((y >> s) & mask))
                       : ((x & mask) | ((y & mask) << s));
    }
    return x;
}

// ---------------------------------------------------------------------------
// K1: IoU adjacency, symmetric 32x32 tiles (upper triangle only).
// Per-block dynamic tile pool (shared atomic) for warp load balance.
// Prologue also zeros: output buffer, g_val, adjacency pad words.
// ---------------------------------------------------------------------------
__global__ __launch_bounds__(K1_THR, 3) void k_adj(
    const float* __restrict__ boxes, float* __restrict__ out, int out_n)
{
    int b = blockIdx.y;
    extern __shared__ float4 sb[];                  // NPAD boxes (x1,y1,x2,y2)
    float* sar = (float*)(sb + NPAD);               // NPAD areas
    __shared__ int sT;

    {
        int gtid = (blockIdx.y * gridDim.x + blockIdx.x) * K1_THR + threadIdx.x;
        int gstr = gridDim.x * gridDim.y * K1_THR;
        int n4 = out_n >> 2;
        float4 z4 = make_float4(0.f, 0.f, 0.f, 0.f);
        for (int i = gtid; i < n4; i += gstr) ((float4*)out)[i] = z4;
        for (int i = (n4 << 2) + gtid; i < out_n; i += gstr) out[i] = 0.f;
        unsigned* gv = &g_val[0][0][0];
        for (int i = gtid; i < NB * NC * NW; i += gstr) gv[i] = 0u;
        unsigned* ga = &g_adj[0][0][0];
        for (int i = gtid; i < NB * NN * (NW - NWU); i += gstr) {
            int r = i / (NW - NWU), w = i - r * (NW - NWU);
            ga[(size_t)r * NW + NWU + w] = 0u;
        }
    }

    int tstart = (blockIdx.x * NTRI) / NXB;
    int tend   = ((blockIdx.x + 1) * NTRI) / NXB;
    if (threadIdx.x == 0) sT = tstart + 12;   // first 12 tiles statically assigned

    const float4* bx = (const float4*)(boxes + (size_t)b * NN * 4);
    for (int i = threadIdx.x; i < NPAD; i += K1_THR) {
        float4 r;
        if (i < NN) {
            float4 v = bx[i];
            float x1 = __fsub_rn(v.x, __fmul_rn(v.z, 0.5f));
            float y1 = __fsub_rn(v.y, __fmul_rn(v.w, 0.5f));
            r = make_float4(x1, y1, __fadd_rn(x1, v.z), __fadd_rn(y1, v.w));
        } else {
            r = make_float4(3e30f, 3e30f, -3e30f, -3e30f);
        }
        sb[i] = r;
        sar[i] = __fmul_rn(__fsub_rn(r.z, r.x), __fsub_rn(r.w, r.y));
    }
    __syncthreads();

    int warp = threadIdx.x >> 5, lane = threadIdx.x & 31;

    int t = tstart + warp;
    while (t < tend) {
        int u = t % NT, v = t / NT;
        int ti, tj;
        if (v <= u) { ti = v; tj = u; }
        else        { ti = NT - v; tj = NT - 1 - u; }
        int ib = ti << 5, jb = tj << 5;

        float4 vc = sb[jb + lane];
        float ac = sar[jb + lane];

        unsigned tw = 0u;
        bool ambAny = false;
#pragma unroll
        for (int r = 0; r < 32; r++) {
            float4 vr = sb[ib + r];
            float ar = sar[ib + r];
            float ltx = fmaxf(vr.x, vc.x);
            float lty = fmaxf(vr.y, vc.y);
            float rbx = fminf(vr.z, vc.z);
            float rby = fminf(vr.w, vc.w);
            float iw = fmaxf(__fsub_rn(rbx, ltx), 0.0f);
            float ih = fmaxf(__fsub_rn(rby, lty), 0.0f);
            float inter = __fmul_rn(iw, ih);
            float den = __fsub_rn(__fadd_rn(ar, ac), inter);
            bool ok = inter > __fmul_rn(den, 0.4000002f);
            bool df = inter < __fmul_rn(den, 0.3999998f);
            ambAny |= (!ok && !df);
            if (ok) tw |= (1u << r);
        }
        if (__any_sync(0xffffffffu, ambAny)) {
            tw = 0u;
#pragma unroll 1
            for (int r = 0; r < 32; r++) {
                float4 vr = sb[ib + r];
                float ar = sar[ib + r];
                float ltx = fmaxf(vr.x, vc.x);
                float lty = fmaxf(vr.y, vc.y);
                float rbx = fminf(vr.z, vc.z);
                float rby = fminf(vr.w, vc.w);
                float iw = fmaxf(__fsub_rn(rbx, ltx), 0.0f);
                float ih = fmaxf(__fsub_rn(rby, lty), 0.0f);
                float inter = __fmul_rn(iw, ih);
                float den = __fsub_rn(__fadd_rn(ar, ac), inter);
                if (__fdiv_rn(inter, den) >= 0.4f) tw |= (1u << r);
            }
        }

        if (ti == tj) {
            tw &= ~(1u << lane);
            int row = jb + lane;
            if (row < NN) g_adj[b][row][ti] = tw;
        } else {
            int row = jb + lane;
            if (row < NN) g_adj[b][row][ti] = tw;
            unsigned x = bit_transpose32(tw, lane);
            int row2 = ib + lane;
            if (row2 < NN) g_adj[b][row2][tj] = x;
        }

        if (lane == 0) t = atomicAdd(&sT, 1);
        t = __shfl_sync(0xffffffffu, t, 0);
    }
}

// ---------------------------------------------------------------------------
// K2: per-box neighbor max of con (all 16 classes) + valid0 bit production.
// ---------------------------------------------------------------------------
__global__ __launch_bounds__(256) void k_valid(
    const float* __restrict__ pro, const float* __restrict__ con,
    const float* __restrict__ conf)
{
    int g = (blockIdx.x * blockDim.x + threadIdx.x) >> 5;
    int lane = threadIdx.x & 31;
    if (g >= NB * NN) return;
    int b = g / NN;
    int i = g - b * NN;

    float4 m0 = make_float4(0.f, 0.f, 0.f, 0.f);
    float4 m1 = m0, m2 = m0, m3 = m0;
    const float4* crow = (const float4*)(con + (size_t)b * NN * NC);
    uint4 wv = ((const uint4*)&g_adj[b][i][0])[lane];

#pragma unroll
    for (int s = 0; s < 4; s++) {
        unsigned m = (s == 0) ? wv.x : (s == 1) ? wv.y : (s == 2) ? wv.z : wv.w;
        int jbase = (lane << 7) + (s << 5);
        while (m) {
            int bit = __ffs(m) - 1;
            m &= m - 1;
            int j = jbase + bit;
            const float4* cj = crow + (size_t)j * 4;
            float4 a = __ldg(cj + 0), bb = __ldg(cj + 1);
            float4 cc = __ldg(cj + 2), dd = __ldg(cj + 3);
            m0.x = fmaxf(m0.x, a.x);  m0.y = fmaxf(m0.y, a.y);
            m0.z = fmaxf(m0.z, a.z);  m0.w = fmaxf(m0.w, a.w);
            m1.x = fmaxf(m1.x, bb.x); m1.y = fmaxf(m1.y, bb.y);
            m1.z = fmaxf(m1.z, bb.z); m1.w = fmaxf(m1.w, bb.w);
            m2.x = fmaxf(m2.x, cc.x); m2.y = fmaxf(m2.y, cc.y);
            m2.z = fmaxf(m2.z, cc.z); m2.w = fmaxf(m2.w, cc.w);
            m3.x = fmaxf(m3.x, dd.x); m3.y = fmaxf(m3.y, dd.y);
            m3.z = fmaxf(m3.z, dd.z); m3.w = fmaxf(m3.w, dd.w);
        }
    }
#define WRED(f) { for (int o = 16; o > 0; o >>= 1) f = fmaxf(f, __shfl_xor_sync(0xffffffffu, f, o)); }
    WRED(m0.x) WRED(m0.y) WRED(m0.z) WRED(m0.w)
    WRED(m1.x) WRED(m1.y) WRED(m1.z) WRED(m1.w)
    WRED(m2.x) WRED(m2.y) WRED(m2.z) WRED(m2.w)
    WRED(m3.x) WRED(m3.y) WRED(m3.z) WRED(m3.w)
#undef WRED

    int c = lane;
    if (c < NC) {
        float4 g1 = (c & 8) ? ((c & 4) ? m3 : m2) : ((c & 4) ? m1 : m0);
        float pa = (c & 2) ? g1.z : g1.x;
        float pb = (c & 2) ? g1.w : g1.y;
        float ac = (c & 1) ? pb : pa;
        size_t base = ((size_t)b * NN + i) * NC + c;
        float pv = pro[base];
        float cv = con[base];
        if (pv >= conf[c] && pv >= cv && pv >= ac)
            atomicOr(&g_val[b][c][i >> 5], 1u << (i & 31));
    }
}

// ---------------------------------------------------------------------------
// K3: per-(image, class) NMS. One block (1024 thr) per (b, c).
// R13 structure: bitonic sort, parallel connectivity, pairwise (2-wide)
// prefetched warp-shfl greedy chain over connected candidates.
// ---------------------------------------------------------------------------
__global__ __launch_bounds__(1024) void k_nms(
    const float* __restrict__ pro, const float* __restrict__ boxes,
    const float* __restrict__ scales, float* __restrict__ out, int maskMode)
{
    __shared__ unsigned long long skey[4096];   // 32 KB
    __shared__ int ssorted[NN];                 // compact list, then survivors
    __shared__ unsigned int svalid[NW];         // 512 B
    __shared__ unsigned int sconn[NW];          // connectivity bits per sorted pos
    __shared__ int scount;
    __shared__ int sS;
    __shared__ int sKC;

    int c = blockIdx.x, b = blockIdx.y;
    int tid = threadIdx.x;
    int lane = tid & 31;

    if (tid == 0) { scount = 0; sS = 0; sKC = 0; }
    if (tid < NW) { svalid[tid] = g_val[b][c][tid]; sconn[tid] = 0u; }
    __syncthreads();

    // -------- candidate gather from valid0 bitmask
    if (tid < NWU) {
        unsigned w = svalid[tid];
        if (w) {
            int pos = atomicAdd(&scount, __popc(w));
            while (w) {
                int bit = __ffs(w) - 1;
                w &= w - 1;
                int idx = (tid << 5) + bit;
                float p = pro[((size_t)b * NN + idx) * NC + c];
                skey[pos++] = ((unsigned long long)__float_as_uint(p) << 32)
                            | (unsigned long long)(0xFFFFFFFFu - (unsigned)idx);
            }
        }
    }
    __syncthreads();
    int K = scount;
    int Kp = 1;
    while (Kp < K) Kp <<= 1;

    for (int t = K + tid; t < Kp; t += blockDim.x) skey[t] = 0ULL;
    __syncthreads();

    // -------- bitonic sort descending (score desc, idx asc — stable argsort)
    for (int k2 = 2; k2 <= Kp; k2 <<= 1) {
        for (int j = k2 >> 1; j > 0; j >>= 1) {
            for (int i = tid; i < Kp; i += blockDim.x) {
                int ixj = i ^ j;
                if (ixj > i) {
                    unsigned long long a = skey[i], bb2 = skey[ixj];
                    bool up = ((i & k2) == 0);
                    if (up ? (a < bb2) : (a > bb2)) { skey[i] = bb2; skey[ixj] = a; }
                }
            }
            __syncthreads();
        }
    }

#define IDXAT(k) ((int)(0xFFFFFFFFu - (unsigned)skey[(k)]))
    // -------- connectivity: does this candidate touch any other candidate?
    for (int k = tid; k < K; k += blockDim.x) {
        int idx = IDXAT(k);
        const uint4* arow = (const uint4*)&g_adj[b][idx][0];
        const uint4* vmsk = (const uint4*)svalid;
        bool conn = false;
#pragma unroll 4
        for (int w = 0; w < 29; w++) {          // 116 words; pads are zero
            uint4 a = __ldg(arow + w);
            uint4 m = vmsk[w];
            if ((a.x & m.x) | (a.y & m.y) | (a.z & m.z) | (a.w & m.w)) { conn = true; break; }
        }
        if (conn) atomicOr(&sconn[k >> 5], 1u << (k & 31));
    }
    __syncthreads();

    // -------- warp 0: compact connected list, then pairwise greedy chain
    if (tid < 32) {
        int baseC = 0;
        for (int k0 = 0; k0 < K; k0 += 32) {
            int kk = k0 + lane;
            bool cn = (kk < K) && ((sconn[kk >> 5] >> (kk & 31)) & 1u);
            unsigned mm = __ballot_sync(0xffffffffu, cn);
            if (cn) ssorted[baseC + __popc(mm & ((1u << lane) - 1u))] = kk;
            baseC += __popc(mm);
        }
        int KC = baseC;
        if (lane == 0) sKC = KC;

        const uint4* adjB = (const uint4*)&g_adj[b][0][0];  // row i -> adjB + i*32
        uint4 v = ((uint4*)svalid)[lane];
        uint4 z = make_uint4(0u, 0u, 0u, 0u);
        uint4 pf0 = z, pf1 = z, pf2 = z, pf3 = z;
        if (KC > 0) pf0 = adjB[(size_t)IDXAT(ssorted[0]) * 32 + lane];
        if (KC > 1) pf1 = adjB[(size_t)IDXAT(ssorted[1]) * 32 + lane];
        if (KC > 2) pf2 = adjB[(size_t)IDXAT(ssorted[2]) * 32 + lane];
        if (KC > 3) pf3 = adjB[(size_t)IDXAT(ssorted[3]) * 32 + lane];

#define WORDSEL(vec, wdq, dst)                                                   \
        switch ((wdq) & 3) {                                                     \
            case 0:  dst = __shfl_sync(0xffffffffu, (vec).x, (wdq) >> 2); break; \
            case 1:  dst = __shfl_sync(0xffffffffu, (vec).y, (wdq) >> 2); break; \
            case 2:  dst = __shfl_sync(0xffffffffu, (vec).z, (wdq) >> 2); break; \
            default: dst = __shfl_sync(0xffffffffu, (vec).w, (wdq) >> 2); break; \
        }
#define GSTEP2(kk, pfa, pfb)                                                  \
        if ((kk) < KC) {                                                      \
            int idxa = IDXAT(ssorted[(kk)]);                                  \
            bool haveB = (kk) + 1 < KC;                                       \
            int idxb = haveB ? IDXAT(ssorted[(kk) + 1]) : idxa;               \
            int wda = idxa >> 5, wdb = idxb >> 5;                             \
            unsigned vwa, vwb, paw;                                           \
            WORDSEL(v, wda, vwa)                                              \
            WORDSEL(v, wdb, vwb)                                              \
            WORDSEL(pfa, wdb, paw)                                            \
            bool aliveA = (vwa >> (idxa & 31)) & 1u;                          \
            bool aliveB = haveB && ((vwb >> (idxb & 31)) & 1u)                \
                        && !(aliveA && ((paw >> (idxb & 31)) & 1u));          \
            if (aliveA) {                                                     \
                v.x &= ~pfa.x; v.y &= ~pfa.y; v.z &= ~pfa.z; v.w &= ~pfa.w;   \
            }                                                                 \
            if (aliveB) {                                                     \
                v.x &= ~pfb.x; v.y &= ~pfb.y; v.z &= ~pfb.z; v.w &= ~pfb.w;   \
            }                                                                 \
            if ((kk) + 4 < KC)                                                \
                pfa = adjB[(size_t)IDXAT(ssorted[(kk) + 4]) * 32 + lane];     \
            if ((kk) + 5 < KC)                                                \
                pfb = adjB[(size_t)IDXAT(ssorted[(kk) + 5]) * 32 + lane];     \
        }
        for (int k = 0; k < KC; k += 4) {
            GSTEP2(k,     pf0, pf1)
            GSTEP2(k + 2, pf2, pf3)
        }
#undef GSTEP2
#undef WORDSEL
        ((uint4*)svalid)[lane] = v;
        __syncwarp();

        // survivor extraction over ALL sorted candidates (final v is exact)
        int base = 0;
        for (int k0 = 0; k0 < K; k0 += 32) {
            int kk = k0 + lane;
            bool sv = false;
            int idx = 0;
            if (kk < K) {
                idx = IDXAT(kk);
                sv = (svalid[idx >> 5] >> (idx & 31)) & 1u;
            }
            unsigned mm = __ballot_sync(0xffffffffu, sv);
            if (sv) ssorted[base + __popc(mm & ((1u << lane) - 1u))] = idx;
            base += __popc(mm);
        }
        if (lane == 0) sS = base;
    }
#undef IDXAT
    __syncthreads();

    // -------- write survivor slots only (rest already zero via k_adj prologue)
    int S = sS;
    float scl = scales[b];
    float* ob = out + ((size_t)(b * NC + c)) * NN * 5;
    for (int t = tid; t < S; t += blockDim.x) {
        int idx = ssorted[t];
        float4 bxv = __ldg(&((const float4*)boxes)[(size_t)b * NN + idx]);
        float bcx = __fmul_rn(bxv.x, scl);
        float bcy = __fmul_rn(bxv.y, scl);
        float hw = __fmul_rn(0.5f, __fmul_rn(bxv.z, scl));
        float hh = __fmul_rn(0.5f, __fmul_rn(bxv.w, scl));
        float* p5 = ob + (size_t)t * 5;
        p5[0] = __fsub_rn(bcx, hw);
        p5[1] = __fsub_rn(bcy, hh);
        p5[2] = __fadd_rn(bcx, hw);
        p5[3] = __fadd_rn(bcy, hh);
        p5[4] = pro[((size_t)b * NN + idx) * NC + c];
    }
    if (maskMode == 1) {
        float* mb = out + (size_t)NB * NC * NN * 5 + (size_t)(b * NC + c) * NN;
        for (int t = tid; t < S; t += blockDim.x) mb[t] = 1.0f;
    } else if (maskMode == 2) {
        unsigned char* mb = (unsigned char*)(out + (size_t)NB * NC * NN * 5)
                          + (size_t)(b * NC + c) * NN;
        for (int t = tid; t < S; t += blockDim.x) mb[t] = 1;
    }
}

// ---------------------------------------------------------------------------
// Launch
// ---------------------------------------------------------------------------
extern "C" void kernel_launch(void* const* d_in, const int* in_sizes, int n_in,
                              void* d_out, int out_size) {
    const float* pro    = (const float*)d_in[0];  // (B,N,C)
    const float* con    = (const float*)d_in[1];  // (B,N,C)
    const float* boxes  = (const float*)d_in[2];  // (B,N,4)
    const float* scales = (const float*)d_in[3];  // (B,)
    const float* conf   = (const float*)d_in[4];  // (C,)
    float* out = (float*)d_out;

    cudaFuncSetAttribute(k_adj, cudaFuncAttributeMaxDynamicSharedMemorySize, K1_SMEM);

    long long T5 = (long long)NB * NC * NN * 5;   // 1,152,000
    long long TM = (long long)NB * NC * NN;       //   230,400
    int maskMode = 0;
    if ((long long)out_size >= T5 + TM) maskMode = 1;       // mask as float
    else if ((long long)out_size > T5)  maskMode = 2;       // mask as bytes

    k_adj<<<dim3(NXB, NB), K1_THR, K1_SMEM>>>(boxes, out, out_size);
    k_valid<<<(NB * NN * 32 + 255) / 256, 256>>>(pro, con, conf);
    k_nms<<<dim3(NC, NB), 1024>>>(pro, boxes, scales, out, maskMode);
}

// round 16
// speedup vs baseline: 1.5325x; 1.5325x over previous
#include <cuda_runtime.h>
#include <cuda_bf16.h>
#include <stdint.h>

#define NB 4
#define NN 3600
#define NC 16
#define NW 128          /* padded adjacency words per row (113 used) */
#define NWU 113         /* ceil(3600/32) */
#define NPAD 3616       /* boxes padded: 113 tiles * 32 */
#define NT 113          /* 32-wide tiles per dimension */
#define NTRI 6441       /* NT*(NT+1)/2 upper-tri tiles */
#define K1_SMEM (NPAD * 16 + NPAD * 4)
#define NXB 111         /* x-blocks in k_adj */
#define K1_THR 384      /* 12 warps */

typedef unsigned long long ull;

// ---------------------------------------------------------------------------
// Scratch (device globals; no allocation)
// ---------------------------------------------------------------------------
__device__ unsigned int g_adj[NB][NN][NW];     // adjacency bitmask (7.4 MB)
__device__ unsigned int g_val[NB][NC][NW];     // valid0 bitmask per (b,c)

__device__ __forceinline__ unsigned bit_transpose32(unsigned x, int lane) {
#pragma unroll
    for (int s = 16; s > 0; s >>= 1) {
        unsigned mask = (s == 16) ? 0x0000FFFFu : (s == 8) ? 0x00FF00FFu
                      : (s == 4) ? 0x0F0F0F0Fu : (s == 2) ? 0x33333333u
                      : 0x55555555u;
        unsigned y = __shfl_xor_sync(0xffffffffu, x, s);
        x = (lane & s) ? ((x & ~mask) | ((y >> s) & mask))
                       : ((x & mask) | ((y & mask) << s));
    }
    return x;
}

// ---------------------------------------------------------------------------
// K1: IoU adjacency, symmetric 32x32 tiles (upper triangle only).
// Per-block dynamic tile pool (shared atomic) for warp load balance.
// Prologue also zeros: output buffer, g_val, adjacency pad words.
// ---------------------------------------------------------------------------
__global__ __launch_bounds__(K1_THR, 3) void k_adj(
    const float* __restrict__ boxes, float* __restrict__ out, int out_n)
{
    int b = blockIdx.y;
    extern __shared__ float4 sb[];                  // NPAD boxes (x1,y1,x2,y2)
    float* sar = (float*)(sb + NPAD);               // NPAD areas
    __shared__ int sT;

    {
        int gtid = (blockIdx.y * gridDim.x + blockIdx.x) * K1_THR + threadIdx.x;
        int gstr = gridDim.x * gridDim.y * K1_THR;
        int n4 = out_n >> 2;
        float4 z4 = make_float4(0.f, 0.f, 0.f, 0.f);
        for (int i = gtid; i < n4; i += gstr) ((float4*)out)[i] = z4;
        for (int i = (n4 << 2) + gtid; i < out_n; i += gstr) out[i] = 0.f;
        unsigned* gv = &g_val[0][0][0];
        for (int i = gtid; i < NB * NC * NW; i += gstr) gv[i] = 0u;
        unsigned* ga = &g_adj[0][0][0];
        for (int i = gtid; i < NB * NN * (NW - NWU); i += gstr) {
            int r = i / (NW - NWU), w = i - r * (NW - NWU);
            ga[(size_t)r * NW + NWU + w] = 0u;
        }
    }

    int tstart = (blockIdx.x * NTRI) / NXB;
    int tend   = ((blockIdx.x + 1) * NTRI) / NXB;
    if (threadIdx.x == 0) sT = tstart + 12;   // first 12 tiles statically assigned

    const float4* bx = (const float4*)(boxes + (size_t)b * NN * 4);
    for (int i = threadIdx.x; i < NPAD; i += K1_THR) {
        float4 r;
        if (i < NN) {
            float4 v = bx[i];
            float x1 = __fsub_rn(v.x, __fmul_rn(v.z, 0.5f));
            float y1 = __fsub_rn(v.y, __fmul_rn(v.w, 0.5f));
            r = make_float4(x1, y1, __fadd_rn(x1, v.z), __fadd_rn(y1, v.w));
        } else {
            r = make_float4(3e30f, 3e30f, -3e30f, -3e30f);
        }
        sb[i] = r;
        sar[i] = __fmul_rn(__fsub_rn(r.z, r.x), __fsub_rn(r.w, r.y));
    }
    __syncthreads();

    int warp = threadIdx.x >> 5, lane = threadIdx.x & 31;

    int t = tstart + warp;
    while (t < tend) {
        int u = t % NT, v = t / NT;
        int ti, tj;
        if (v <= u) { ti = v; tj = u; }
        else        { ti = NT - v; tj = NT - 1 - u; }
        int ib = ti << 5, jb = tj << 5;

        float4 vc = sb[jb + lane];
        float ac = sar[jb + lane];

        unsigned tw = 0u;
        bool ambAny = false;
#pragma unroll
        for (int r = 0; r < 32; r++) {
            float4 vr = sb[ib + r];
            float ar = sar[ib + r];
            float ltx = fmaxf(vr.x, vc.x);
            float lty = fmaxf(vr.y, vc.y);
            float rbx = fminf(vr.z, vc.z);
            float rby = fminf(vr.w, vc.w);
            float iw = fmaxf(__fsub_rn(rbx, ltx), 0.0f);
            float ih = fmaxf(__fsub_rn(rby, lty), 0.0f);
            float inter = __fmul_rn(iw, ih);
            float den = __fsub_rn(__fadd_rn(ar, ac), inter);
            bool ok = inter > __fmul_rn(den, 0.4000002f);
            bool df = inter < __fmul_rn(den, 0.3999998f);
            ambAny |= (!ok && !df);
            if (ok) tw |= (1u << r);
        }
        if (__any_sync(0xffffffffu, ambAny)) {
            tw = 0u;
#pragma unroll 1
            for (int r = 0; r < 32; r++) {
                float4 vr = sb[ib + r];
                float ar = sar[ib + r];
                float ltx = fmaxf(vr.x, vc.x);
                float lty = fmaxf(vr.y, vc.y);
                float rbx = fminf(vr.z, vc.z);
                float rby = fminf(vr.w, vc.w);
                float iw = fmaxf(__fsub_rn(rbx, ltx), 0.0f);
                float ih = fmaxf(__fsub_rn(rby, lty), 0.0f);
                float inter = __fmul_rn(iw, ih);
                float den = __fsub_rn(__fadd_rn(ar, ac), inter);
                if (__fdiv_rn(inter, den) >= 0.4f) tw |= (1u << r);
            }
        }

        if (ti == tj) {
            tw &= ~(1u << lane);
            int row = jb + lane;
            if (row < NN) g_adj[b][row][ti] = tw;
        } else {
            int row = jb + lane;
            if (row < NN) g_adj[b][row][ti] = tw;
            unsigned x = bit_transpose32(tw, lane);
            int row2 = ib + lane;
            if (row2 < NN) g_adj[b][row2][tj] = x;
        }

        if (lane == 0) t = atomicAdd(&sT, 1);
        t = __shfl_sync(0xffffffffu, t, 0);
    }
}

// ---------------------------------------------------------------------------
// K2: per-box neighbor max of con (all 16 classes) + valid0 bit production.
// ---------------------------------------------------------------------------
__global__ __launch_bounds__(256) void k_valid(
    const float* __restrict__ pro, const float* __restrict__ con,
    const float* __restrict__ conf)
{
    int g = (blockIdx.x * blockDim.x + threadIdx.x) >> 5;
    int lane = threadIdx.x & 31;
    if (g >= NB * NN) return;
    int b = g / NN;
    int i = g - b * NN;

    float4 m0 = make_float4(0.f, 0.f, 0.f, 0.f);
    float4 m1 = m0, m2 = m0, m3 = m0;
    const float4* crow = (const float4*)(con + (size_t)b * NN * NC);
    uint4 wv = ((const uint4*)&g_adj[b][i][0])[lane];

#pragma unroll
    for (int s = 0; s < 4; s++) {
        unsigned m = (s == 0) ? wv.x : (s == 1) ? wv.y : (s == 2) ? wv.z : wv.w;
        int jbase = (lane << 7) + (s << 5);
        while (m) {
            int bit = __ffs(m) - 1;
            m &= m - 1;
            int j = jbase + bit;
            const float4* cj = crow + (size_t)j * 4;
            float4 a = __ldg(cj + 0), bb = __ldg(cj + 1);
            float4 cc = __ldg(cj + 2), dd = __ldg(cj + 3);
            m0.x = fmaxf(m0.x, a.x);  m0.y = fmaxf(m0.y, a.y);
            m0.z = fmaxf(m0.z, a.z);  m0.w = fmaxf(m0.w, a.w);
            m1.x = fmaxf(m1.x, bb.x); m1.y = fmaxf(m1.y, bb.y);
            m1.z = fmaxf(m1.z, bb.z); m1.w = fmaxf(m1.w, bb.w);
            m2.x = fmaxf(m2.x, cc.x); m2.y = fmaxf(m2.y, cc.y);
            m2.z = fmaxf(m2.z, cc.z); m2.w = fmaxf(m2.w, cc.w);
            m3.x = fmaxf(m3.x, dd.x); m3.y = fmaxf(m3.y, dd.y);
            m3.z = fmaxf(m3.z, dd.z); m3.w = fmaxf(m3.w, dd.w);
        }
    }
#define WRED(f) { for (int o = 16; o > 0; o >>= 1) f = fmaxf(f, __shfl_xor_sync(0xffffffffu, f, o)); }
    WRED(m0.x) WRED(m0.y) WRED(m0.z) WRED(m0.w)
    WRED(m1.x) WRED(m1.y) WRED(m1.z) WRED(m1.w)
    WRED(m2.x) WRED(m2.y) WRED(m2.z) WRED(m2.w)
    WRED(m3.x) WRED(m3.y) WRED(m3.z) WRED(m3.w)
#undef WRED

    int c = lane;
    if (c < NC) {
        float4 g1 = (c & 8) ? ((c & 4) ? m3 : m2) : ((c & 4) ? m1 : m0);
        float pa = (c & 2) ? g1.z : g1.x;
        float pb = (c & 2) ? g1.w : g1.y;
        float ac = (c & 1) ? pb : pa;
        size_t base = ((size_t)b * NN + i) * NC + c;
        float pv = pro[base];
        float cv = con[base];
        if (pv >= conf[c] && pv >= cv && pv >= ac)
            atomicOr(&g_val[b][c][i >> 5], 1u << (i & 31));
    }
}

// ---------------------------------------------------------------------------
// K3: per-(image, class) NMS. One block (512 thr) per (b, c).
// Bitonic sort, parallel connectivity, pairwise (2-wide) prefetched
// warp-shfl greedy chain over connected candidates.  (R13 — measured best.)
// ---------------------------------------------------------------------------
__global__ __launch_bounds__(512) void k_nms(
    const float* __restrict__ pro, const float* __restrict__ boxes,
    const float* __restrict__ scales, float* __restrict__ out, int maskMode)
{
    __shared__ unsigned long long skey[4096];   // 32 KB
    __shared__ int ssorted[NN];                 // compact list, then survivors
    __shared__ unsigned int svalid[NW];         // 512 B
    __shared__ unsigned int sconn[NW];          // connectivity bits per sorted pos
    __shared__ int scount;
    __shared__ int sS;
    __shared__ int sKC;

    int c = blockIdx.x, b = blockIdx.y;
    int tid = threadIdx.x;
    int lane = tid & 31;

    if (tid == 0) { scount = 0; sS = 0; sKC = 0; }
    if (tid < NW) { svalid[tid] = g_val[b][c][tid]; sconn[tid] = 0u; }
    __syncthreads();

    // -------- candidate gather from valid0 bitmask
    if (tid < NWU) {
        unsigned w = svalid[tid];
        if (w) {
            int pos = atomicAdd(&scount, __popc(w));
            while (w) {
                int bit = __ffs(w) - 1;
                w &= w - 1;
                int idx = (tid << 5) + bit;
                float p = pro[((size_t)b * NN + idx) * NC + c];
                skey[pos++] = ((unsigned long long)__float_as_uint(p) << 32)
                            | (unsigned long long)(0xFFFFFFFFu - (unsigned)idx);
            }
        }
    }
    __syncthreads();
    int K = scount;
    int Kp = 1;
    while (Kp < K) Kp <<= 1;

    for (int t = K + tid; t < Kp; t += blockDim.x) skey[t] = 0ULL;
    __syncthreads();

    // -------- bitonic sort descending (score desc, idx asc — stable argsort)
    for (int k2 = 2; k2 <= Kp; k2 <<= 1) {
        for (int j = k2 >> 1; j > 0; j >>= 1) {
            for (int i = tid; i < Kp; i += blockDim.x) {
                int ixj = i ^ j;
                if (ixj > i) {
                    unsigned long long a = skey[i], bb2 = skey[ixj];
                    bool up = ((i & k2) == 0);
                    if (up ? (a < bb2) : (a > bb2)) { skey[i] = bb2; skey[ixj] = a; }
                }
            }
            __syncthreads();
        }
    }

#define IDXAT(k) ((int)(0xFFFFFFFFu - (unsigned)skey[(k)]))
    // -------- connectivity: does this candidate touch any other candidate?
    for (int k = tid; k < K; k += blockDim.x) {
        int idx = IDXAT(k);
        const uint4* arow = (const uint4*)&g_adj[b][idx][0];
        const uint4* vmsk = (const uint4*)svalid;
        bool conn = false;
#pragma unroll 4
        for (int w = 0; w < 29; w++) {          // 116 words; pads are zero
            uint4 a = __ldg(arow + w);
            uint4 m = vmsk[w];
            if ((a.x & m.x) | (a.y & m.y) | (a.z & m.z) | (a.w & m.w)) { conn = true; break; }
        }
        if (conn) atomicOr(&sconn[k >> 5], 1u << (k & 31));
    }
    __syncthreads();

    // -------- warp 0: compact connected list, then pairwise greedy chain
    if (tid < 32) {
        int baseC = 0;
        for (int k0 = 0; k0 < K; k0 += 32) {
            int kk = k0 + lane;
            bool cn = (kk < K) && ((sconn[kk >> 5] >> (kk & 31)) & 1u);
            unsigned mm = __ballot_sync(0xffffffffu, cn);
            if (cn) ssorted[baseC + __popc(mm & ((1u << lane) - 1u))] = kk;
            baseC += __popc(mm);
        }
        int KC = baseC;
        if (lane == 0) sKC = KC;

        const uint4* adjB = (const uint4*)&g_adj[b][0][0];  // row i -> adjB + i*32
        uint4 v = ((uint4*)svalid)[lane];
        uint4 z = make_uint4(0u, 0u, 0u, 0u);
        uint4 pf0 = z, pf1 = z, pf2 = z, pf3 = z;
        if (KC > 0) pf0 = adjB[(size_t)IDXAT(ssorted[0]) * 32 + lane];
        if (KC > 1) pf1 = adjB[(size_t)IDXAT(ssorted[1]) * 32 + lane];
        if (KC > 2) pf2 = adjB[(size_t)IDXAT(ssorted[2]) * 32 + lane];
        if (KC > 3) pf3 = adjB[(size_t)IDXAT(ssorted[3]) * 32 + lane];

#define WORDSEL(vec, wdq, dst)                                                   \
        switch ((wdq) & 3) {                                                     \
            case 0:  dst = __shfl_sync(0xffffffffu, (vec).x, (wdq) >> 2); break; \
            case 1:  dst = __shfl_sync(0xffffffffu, (vec).y, (wdq) >> 2); break; \
            case 2:  dst = __shfl_sync(0xffffffffu, (vec).z, (wdq) >> 2); break; \
            default: dst = __shfl_sync(0xffffffffu, (vec).w, (wdq) >> 2); break; \
        }
#define GSTEP2(kk, pfa, pfb)                                                  \
        if ((kk) < KC) {                                                      \
            int idxa = IDXAT(ssorted[(kk)]);                                  \
            bool haveB = (kk) + 1 < KC;                                       \
            int idxb = haveB ? IDXAT(ssorted[(kk) + 1]) : idxa;               \
            int wda = idxa >> 5, wdb = idxb >> 5;                             \
            unsigned vwa, vwb, paw;                                           \
            WORDSEL(v, wda, vwa)                                              \
            WORDSEL(v, wdb, vwb)                                              \
            WORDSEL(pfa, wdb, paw)                                            \
            bool aliveA = (vwa >> (idxa & 31)) & 1u;                          \
            bool aliveB = haveB && ((vwb >> (idxb & 31)) & 1u)                \
                        && !(aliveA && ((paw >> (idxb & 31)) & 1u));          \
            if (aliveA) {                                                     \
                v.x &= ~pfa.x; v.y &= ~pfa.y; v.z &= ~pfa.z; v.w &= ~pfa.w;   \
            }                                                                 \
            if (aliveB) {                                                     \
                v.x &= ~pfb.x; v.y &= ~pfb.y; v.z &= ~pfb.z; v.w &= ~pfb.w;   \
            }                                                                 \
            if ((kk) + 4 < KC)                                                \
                pfa = adjB[(size_t)IDXAT(ssorted[(kk) + 4]) * 32 + lane];     \
            if ((kk) + 5 < KC)                                                \
                pfb = adjB[(size_t)IDXAT(ssorted[(kk) + 5]) * 32 + lane];     \
        }
        for (int k = 0; k < KC; k += 4) {
            GSTEP2(k,     pf0, pf1)
            GSTEP2(k + 2, pf2, pf3)
        }
#undef GSTEP2
#undef WORDSEL
        ((uint4*)svalid)[lane] = v;
        __syncwarp();

        // survivor extraction over ALL sorted candidates (final v is exact)
        int base = 0;
        for (int k0 = 0; k0 < K; k0 += 32) {
            int kk = k0 + lane;
            bool sv = false;
            int idx = 0;
            if (kk < K) {
                idx = IDXAT(kk);
                sv = (svalid[idx >> 5] >> (idx & 31)) & 1u;
            }
            unsigned mm = __ballot_sync(0xffffffffu, sv);
            if (sv) ssorted[base + __popc(mm & ((1u << lane) - 1u))] = idx;
            base += __popc(mm);
        }
        if (lane == 0) sS = base;
    }
#undef IDXAT
    __syncthreads();

    // -------- write survivor slots only (rest already zero via k_adj prologue)
    int S = sS;
    float scl = scales[b];
    float* ob = out + ((size_t)(b * NC + c)) * NN * 5;
    for (int t = tid; t < S; t += blockDim.x) {
        int idx = ssorted[t];
        float4 bxv = __ldg(&((const float4*)boxes)[(size_t)b * NN + idx]);
        float bcx = __fmul_rn(bxv.x, scl);
        float bcy = __fmul_rn(bxv.y, scl);
        float hw = __fmul_rn(0.5f, __fmul_rn(bxv.z, scl));
        float hh = __fmul_rn(0.5f, __fmul_rn(bxv.w, scl));
        float* p5 = ob + (size_t)t * 5;
        p5[0] = __fsub_rn(bcx, hw);
        p5[1] = __fsub_rn(bcy, hh);
        p5[2] = __fadd_rn(bcx, hw);
        p5[3] = __fadd_rn(bcy, hh);
        p5[4] = pro[((size_t)b * NN + idx) * NC + c];
    }
    if (maskMode == 1) {
        float* mb = out + (size_t)NB * NC * NN * 5 + (size_t)(b * NC + c) * NN;
        for (int t = tid; t < S; t += blockDim.x) mb[t] = 1.0f;
    } else if (maskMode == 2) {
        unsigned char* mb = (unsigned char*)(out + (size_t)NB * NC * NN * 5)
                          + (size_t)(b * NC + c) * NN;
        for (int t = tid; t < S; t += blockDim.x) mb[t] = 1;
    }
}

// ---------------------------------------------------------------------------
// Launch
// ---------------------------------------------------------------------------
extern "C" void kernel_launch(void* const* d_in, const int* in_sizes, int n_in,
                              void* d_out, int out_size) {
    const float* pro    = (const float*)d_in[0];  // (B,N,C)
    const float* con    = (const float*)d_in[1];  // (B,N,C)
    const float* boxes  = (const float*)d_in[2];  // (B,N,4)
    const float* scales = (const float*)d_in[3];  // (B,)
    const float* conf   = (const float*)d_in[4];  // (C,)
    float* out = (float*)d_out;

    cudaFuncSetAttribute(k_adj, cudaFuncAttributeMaxDynamicSharedMemorySize, K1_SMEM);

    long long T5 = (long long)NB * NC * NN * 5;   // 1,152,000
    long long TM = (long long)NB * NC * NN;       //   230,400
    int maskMode = 0;
    if ((long long)out_size >= T5 + TM) maskMode = 1;       // mask as float
    else if ((long long)out_size > T5)  maskMode = 2;       // mask as bytes

    k_adj<<<dim3(NXB, NB), K1_THR, K1_SMEM>>>(boxes, out, out_size);
    k_valid<<<(NB * NN * 32 + 255) / 256, 256>>>(pro, con, conf);
    k_nms<<<dim3(NC, NB), 512>>>(pro, boxes, scales, out, maskMode);
}

// round 17
// speedup vs baseline: 1.5644x; 1.0208x over previous
#include <cuda_runtime.h>
#include <cuda_bf16.h>
#include <stdint.h>

#define NB 4
#define NN 3600
#define NC 16
#define NW 128          /* padded adjacency words per row (113 used) */
#define NWU 113         /* ceil(3600/32) */
#define NPAD 3616       /* boxes padded: 113 tiles * 32 */
#define NT 113          /* 32-wide tiles per dimension */
#define NTRI 6441       /* NT*(NT+1)/2 upper-tri tiles */
#define K1_SMEM (NPAD * 16 + NPAD * 4)
#define NXB 111         /* x-blocks in k_adj */
#define K1_THR 384      /* 12 warps */

typedef unsigned long long ull;

// ---------------------------------------------------------------------------
// Scratch (device globals; no allocation)
// ---------------------------------------------------------------------------
__device__ unsigned int g_adj[NB][NN][NW];     // adjacency bitmask (7.4 MB)
__device__ unsigned int g_val[NB][NC][NW];     // valid0 bitmask per (b,c)

__device__ __forceinline__ unsigned bit_transpose32(unsigned x, int lane) {
#pragma unroll
    for (int s = 16; s > 0; s >>= 1) {
        unsigned mask = (s == 16) ? 0x0000FFFFu : (s == 8) ? 0x00FF00FFu
                      : (s == 4) ? 0x0F0F0F0Fu : (s == 2) ? 0x33333333u
                      : 0x55555555u;
        unsigned y = __shfl_xor_sync(0xffffffffu, x, s);
        x = (lane & s) ? ((x & ~mask) | ((y >> s) & mask))
                       : ((x & mask) | ((y & mask) << s));
    }
    return x;
}

// ---------------------------------------------------------------------------
// K1: IoU adjacency, symmetric 32x32 tiles (upper triangle only).
// Per-block dynamic tile pool (shared atomic) for warp load balance.
// Prologue also zeros: output buffer, g_val, adjacency pad words.
// NOTE: no min-blocks clause — let registers float for deeper pipelining
// (occupancy drops to 2 blocks/SM; measured irrelevant across 34-46% occ).
// ---------------------------------------------------------------------------
__global__ __launch_bounds__(K1_THR) void k_adj(
    const float* __restrict__ boxes, float* __restrict__ out, int out_n)
{
    int b = blockIdx.y;
    extern __shared__ float4 sb[];                  // NPAD boxes (x1,y1,x2,y2)
    float* sar = (float*)(sb + NPAD);               // NPAD areas
    __shared__ int sT;

    {
        int gtid = (blockIdx.y * gridDim.x + blockIdx.x) * K1_THR + threadIdx.x;
        int gstr = gridDim.x * gridDim.y * K1_THR;
        int n4 = out_n >> 2;
        float4 z4 = make_float4(0.f, 0.f, 0.f, 0.f);
        for (int i = gtid; i < n4; i += gstr) ((float4*)out)[i] = z4;
        for (int i = (n4 << 2) + gtid; i < out_n; i += gstr) out[i] = 0.f;
        unsigned* gv = &g_val[0][0][0];
        for (int i = gtid; i < NB * NC * NW; i += gstr) gv[i] = 0u;
        unsigned* ga = &g_adj[0][0][0];
        for (int i = gtid; i < NB * NN * (NW - NWU); i += gstr) {
            int r = i / (NW - NWU), w = i - r * (NW - NWU);
            ga[(size_t)r * NW + NWU + w] = 0u;
        }
    }

    int tstart = (blockIdx.x * NTRI) / NXB;
    int tend   = ((blockIdx.x + 1) * NTRI) / NXB;
    if (threadIdx.x == 0) sT = tstart + 12;   // first 12 tiles statically assigned

    const float4* bx = (const float4*)(boxes + (size_t)b * NN * 4);
    for (int i = threadIdx.x; i < NPAD; i += K1_THR) {
        float4 r;
        if (i < NN) {
            float4 v = bx[i];
            float x1 = __fsub_rn(v.x, __fmul_rn(v.z, 0.5f));
            float y1 = __fsub_rn(v.y, __fmul_rn(v.w, 0.5f));
            r = make_float4(x1, y1, __fadd_rn(x1, v.z), __fadd_rn(y1, v.w));
        } else {
            r = make_float4(3e30f, 3e30f, -3e30f, -3e30f);
        }
        sb[i] = r;
        sar[i] = __fmul_rn(__fsub_rn(r.z, r.x), __fsub_rn(r.w, r.y));
    }
    __syncthreads();

    int warp = threadIdx.x >> 5, lane = threadIdx.x & 31;

    int t = tstart + warp;
    while (t < tend) {
        int u = t % NT, v = t / NT;
        int ti, tj;
        if (v <= u) { ti = v; tj = u; }
        else        { ti = NT - v; tj = NT - 1 - u; }
        int ib = ti << 5, jb = tj << 5;

        float4 vc = sb[jb + lane];
        float ac = sar[jb + lane];

        unsigned tw = 0u;
        bool ambAny = false;
#pragma unroll
        for (int r = 0; r < 32; r++) {
            float4 vr = sb[ib + r];
            float ar = sar[ib + r];
            float ltx = fmaxf(vr.x, vc.x);
            float lty = fmaxf(vr.y, vc.y);
            float rbx = fminf(vr.z, vc.z);
            float rby = fminf(vr.w, vc.w);
            float iw = fmaxf(__fsub_rn(rbx, ltx), 0.0f);
            float ih = fmaxf(__fsub_rn(rby, lty), 0.0f);
            float inter = __fmul_rn(iw, ih);
            float den = __fsub_rn(__fadd_rn(ar, ac), inter);
            bool ok = inter > __fmul_rn(den, 0.4000002f);
            bool df = inter < __fmul_rn(den, 0.3999998f);
            ambAny |= (!ok && !df);
            if (ok) tw |= (1u << r);
        }
        if (__any_sync(0xffffffffu, ambAny)) {
            tw = 0u;
#pragma unroll 1
            for (int r = 0; r < 32; r++) {
                float4 vr = sb[ib + r];
                float ar = sar[ib + r];
                float ltx = fmaxf(vr.x, vc.x);
                float lty = fmaxf(vr.y, vc.y);
                float rbx = fminf(vr.z, vc.z);
                float rby = fminf(vr.w, vc.w);
                float iw = fmaxf(__fsub_rn(rbx, ltx), 0.0f);
                float ih = fmaxf(__fsub_rn(rby, lty), 0.0f);
                float inter = __fmul_rn(iw, ih);
                float den = __fsub_rn(__fadd_rn(ar, ac), inter);
                if (__fdiv_rn(inter, den) >= 0.4f) tw |= (1u << r);
            }
        }

        if (ti == tj) {
            tw &= ~(1u << lane);
            int row = jb + lane;
            if (row < NN) g_adj[b][row][ti] = tw;
        } else {
            int row = jb + lane;
            if (row < NN) g_adj[b][row][ti] = tw;
            unsigned x = bit_transpose32(tw, lane);
            int row2 = ib + lane;
            if (row2 < NN) g_adj[b][row2][tj] = x;
        }

        if (lane == 0) t = atomicAdd(&sT, 1);
        t = __shfl_sync(0xffffffffu, t, 0);
    }
}

// ---------------------------------------------------------------------------
// K2: per-box neighbor max of con (all 16 classes) + valid0 bit production.
// ---------------------------------------------------------------------------
__global__ __launch_bounds__(256) void k_valid(
    const float* __restrict__ pro, const float* __restrict__ con,
    const float* __restrict__ conf)
{
    int g = (blockIdx.x * blockDim.x + threadIdx.x) >> 5;
    int lane = threadIdx.x & 31;
    if (g >= NB * NN) return;
    int b = g / NN;
    int i = g - b * NN;

    float4 m0 = make_float4(0.f, 0.f, 0.f, 0.f);
    float4 m1 = m0, m2 = m0, m3 = m0;
    const float4* crow = (const float4*)(con + (size_t)b * NN * NC);
    uint4 wv = ((const uint4*)&g_adj[b][i][0])[lane];

#pragma unroll
    for (int s = 0; s < 4; s++) {
        unsigned m = (s == 0) ? wv.x : (s == 1) ? wv.y : (s == 2) ? wv.z : wv.w;
        int jbase = (lane << 7) + (s << 5);
        while (m) {
            int bit = __ffs(m) - 1;
            m &= m - 1;
            int j = jbase + bit;
            const float4* cj = crow + (size_t)j * 4;
            float4 a = __ldg(cj + 0), bb = __ldg(cj + 1);
            float4 cc = __ldg(cj + 2), dd = __ldg(cj + 3);
            m0.x = fmaxf(m0.x, a.x);  m0.y = fmaxf(m0.y, a.y);
            m0.z = fmaxf(m0.z, a.z);  m0.w = fmaxf(m0.w, a.w);
            m1.x = fmaxf(m1.x, bb.x); m1.y = fmaxf(m1.y, bb.y);
            m1.z = fmaxf(m1.z, bb.z); m1.w = fmaxf(m1.w, bb.w);
            m2.x = fmaxf(m2.x, cc.x); m2.y = fmaxf(m2.y, cc.y);
            m2.z = fmaxf(m2.z, cc.z); m2.w = fmaxf(m2.w, cc.w);
            m3.x = fmaxf(m3.x, dd.x); m3.y = fmaxf(m3.y, dd.y);
            m3.z = fmaxf(m3.z, dd.z); m3.w = fmaxf(m3.w, dd.w);
        }
    }
#define WRED(f) { for (int o = 16; o > 0; o >>= 1) f = fmaxf(f, __shfl_xor_sync(0xffffffffu, f, o)); }
    WRED(m0.x) WRED(m0.y) WRED(m0.z) WRED(m0.w)
    WRED(m1.x) WRED(m1.y) WRED(m1.z) WRED(m1.w)
    WRED(m2.x) WRED(m2.y) WRED(m2.z) WRED(m2.w)
    WRED(m3.x) WRED(m3.y) WRED(m3.z) WRED(m3.w)
#undef WRED

    int c = lane;
    if (c < NC) {
        float4 g1 = (c & 8) ? ((c & 4) ? m3 : m2) : ((c & 4) ? m1 : m0);
        float pa = (c & 2) ? g1.z : g1.x;
        float pb = (c & 2) ? g1.w : g1.y;
        float ac = (c & 1) ? pb : pa;
        size_t base = ((size_t)b * NN + i) * NC + c;
        float pv = pro[base];
        float cv = con[base];
        if (pv >= conf[c] && pv >= cv && pv >= ac)
            atomicOr(&g_val[b][c][i >> 5], 1u << (i & 31));
    }
}

// ---------------------------------------------------------------------------
// K3: per-(image, class) NMS. One block (512 thr) per (b, c).
// Bitonic sort, parallel connectivity, pairwise (2-wide) prefetched
// warp-shfl greedy chain over connected candidates.  (R13/R16 — measured best.)
// ---------------------------------------------------------------------------
__global__ __launch_bounds__(512) void k_nms(
    const float* __restrict__ pro, const float* __restrict__ boxes,
    const float* __restrict__ scales, float* __restrict__ out, int maskMode)
{
    __shared__ unsigned long long skey[4096];   // 32 KB
    __shared__ int ssorted[NN];                 // compact list, then survivors
    __shared__ unsigned int svalid[NW];         // 512 B
    __shared__ unsigned int sconn[NW];          // connectivity bits per sorted pos
    __shared__ int scount;
    __shared__ int sS;
    __shared__ int sKC;

    int c = blockIdx.x, b = blockIdx.y;
    int tid = threadIdx.x;
    int lane = tid & 31;

    if (tid == 0) { scount = 0; sS = 0; sKC = 0; }
    if (tid < NW) { svalid[tid] = g_val[b][c][tid]; sconn[tid] = 0u; }
    __syncthreads();

    // -------- candidate gather from valid0 bitmask
    if (tid < NWU) {
        unsigned w = svalid[tid];
        if (w) {
            int pos = atomicAdd(&scount, __popc(w));
            while (w) {
                int bit = __ffs(w) - 1;
                w &= w - 1;
                int idx = (tid << 5) + bit;
                float p = pro[((size_t)b * NN + idx) * NC + c];
                skey[pos++] = ((unsigned long long)__float_as_uint(p) << 32)
                            | (unsigned long long)(0xFFFFFFFFu - (unsigned)idx);
            }
        }
    }
    __syncthreads();
    int K = scount;
    int Kp = 1;
    while (Kp < K) Kp <<= 1;

    for (int t = K + tid; t < Kp; t += blockDim.x) skey[t] = 0ULL;
    __syncthreads();

    // -------- bitonic sort descending (score desc, idx asc — stable argsort)
    for (int k2 = 2; k2 <= Kp; k2 <<= 1) {
        for (int j = k2 >> 1; j > 0; j >>= 1) {
            for (int i = tid; i < Kp; i += blockDim.x) {
                int ixj = i ^ j;
                if (ixj > i) {
                    unsigned long long a = skey[i], bb2 = skey[ixj];
                    bool up = ((i & k2) == 0);
                    if (up ? (a < bb2) : (a > bb2)) { skey[i] = bb2; skey[ixj] = a; }
                }
            }
            __syncthreads();
        }
    }

#define IDXAT(k) ((int)(0xFFFFFFFFu - (unsigned)skey[(k)]))
    // -------- connectivity: does this candidate touch any other candidate?
    for (int k = tid; k < K; k += blockDim.x) {
        int idx = IDXAT(k);
        const uint4* arow = (const uint4*)&g_adj[b][idx][0];
        const uint4* vmsk = (const uint4*)svalid;
        bool conn = false;
#pragma unroll 4
        for (int w = 0; w < 29; w++) {          // 116 words; pads are zero
            uint4 a = __ldg(arow + w);
            uint4 m = vmsk[w];
            if ((a.x & m.x) | (a.y & m.y) | (a.z & m.z) | (a.w & m.w)) { conn = true; break; }
        }
        if (conn) atomicOr(&sconn[k >> 5], 1u << (k & 31));
    }
    __syncthreads();

    // -------- warp 0: compact connected list, then pairwise greedy chain
    if (tid < 32) {
        int baseC = 0;
        for (int k0 = 0; k0 < K; k0 += 32) {
            int kk = k0 + lane;
            bool cn = (kk < K) && ((sconn[kk >> 5] >> (kk & 31)) & 1u);
            unsigned mm = __ballot_sync(0xffffffffu, cn);
            if (cn) ssorted[baseC + __popc(mm & ((1u << lane) - 1u))] = kk;
            baseC += __popc(mm);
        }
        int KC = baseC;
        if (lane == 0) sKC = KC;

        const uint4* adjB = (const uint4*)&g_adj[b][0][0];  // row i -> adjB + i*32
        uint4 v = ((uint4*)svalid)[lane];
        uint4 z = make_uint4(0u, 0u, 0u, 0u);
        uint4 pf0 = z, pf1 = z, pf2 = z, pf3 = z;
        if (KC > 0) pf0 = adjB[(size_t)IDXAT(ssorted[0]) * 32 + lane];
        if (KC > 1) pf1 = adjB[(size_t)IDXAT(ssorted[1]) * 32 + lane];
        if (KC > 2) pf2 = adjB[(size_t)IDXAT(ssorted[2]) * 32 + lane];
        if (KC > 3) pf3 = adjB[(size_t)IDXAT(ssorted[3]) * 32 + lane];

#define WORDSEL(vec, wdq, dst)                                                   \
        switch ((wdq) & 3) {                                                     \
            case 0:  dst = __shfl_sync(0xffffffffu, (vec).x, (wdq) >> 2); break; \
            case 1:  dst = __shfl_sync(0xffffffffu, (vec).y, (wdq) >> 2); break; \
            case 2:  dst = __shfl_sync(0xffffffffu, (vec).z, (wdq) >> 2); break; \
            default: dst = __shfl_sync(0xffffffffu, (vec).w, (wdq) >> 2); break; \
        }
#define GSTEP2(kk, pfa, pfb)                                                  \
        if ((kk) < KC) {                                                      \
            int idxa = IDXAT(ssorted[(kk)]);                                  \
            bool haveB = (kk) + 1 < KC;                                       \
            int idxb = haveB ? IDXAT(ssorted[(kk) + 1]) : idxa;               \
            int wda = idxa >> 5, wdb = idxb >> 5;                             \
            unsigned vwa, vwb, paw;                                           \
            WORDSEL(v, wda, vwa)                                              \
            WORDSEL(v, wdb, vwb)                                              \
            WORDSEL(pfa, wdb, paw)                                            \
            bool aliveA = (vwa >> (idxa & 31)) & 1u;                          \
            bool aliveB = haveB && ((vwb >> (idxb & 31)) & 1u)                \
                        && !(aliveA && ((paw >> (idxb & 31)) & 1u));          \
            if (aliveA) {                                                     \
                v.x &= ~pfa.x; v.y &= ~pfa.y; v.z &= ~pfa.z; v.w &= ~pfa.w;   \
            }                                                                 \
            if (aliveB) {                                                     \
                v.x &= ~pfb.x; v.y &= ~pfb.y; v.z &= ~pfb.z; v.w &= ~pfb.w;   \
            }                                                                 \
            if ((kk) + 4 < KC)                                                \
                pfa = adjB[(size_t)IDXAT(ssorted[(kk) + 4]) * 32 + lane];     \
            if ((kk) + 5 < KC)                                                \
                pfb = adjB[(size_t)IDXAT(ssorted[(kk) + 5]) * 32 + lane];     \
        }
        for (int k = 0; k < KC; k += 4) {
            GSTEP2(k,     pf0, pf1)
            GSTEP2(k + 2, pf2, pf3)
        }
#undef GSTEP2
#undef WORDSEL
        ((uint4*)svalid)[lane] = v;
        __syncwarp();

        // survivor extraction over ALL sorted candidates (final v is exact)
        int base = 0;
        for (int k0 = 0; k0 < K; k0 += 32) {
            int kk = k0 + lane;
            bool sv = false;
            int idx = 0;
            if (kk < K) {
                idx = IDXAT(kk);
                sv = (svalid[idx >> 5] >> (idx & 31)) & 1u;
            }
            unsigned mm = __ballot_sync(0xffffffffu, sv);
            if (sv) ssorted[base + __popc(mm & ((1u << lane) - 1u))] = idx;
            base += __popc(mm);
        }
        if (lane == 0) sS = base;
    }
#undef IDXAT
    __syncthreads();

    // -------- write survivor slots only (rest already zero via k_adj prologue)
    int S = sS;
    float scl = scales[b];
    float* ob = out + ((size_t)(b * NC + c)) * NN * 5;
    for (int t = tid; t < S; t += blockDim.x) {
        int idx = ssorted[t];
        float4 bxv = __ldg(&((const float4*)boxes)[(size_t)b * NN + idx]);
        float bcx = __fmul_rn(bxv.x, scl);
        float bcy = __fmul_rn(bxv.y, scl);
        float hw = __fmul_rn(0.5f, __fmul_rn(bxv.z, scl));
        float hh = __fmul_rn(0.5f, __fmul_rn(bxv.w, scl));
        float* p5 = ob + (size_t)t * 5;
        p5[0] = __fsub_rn(bcx, hw);
        p5[1] = __fsub_rn(bcy, hh);
        p5[2] = __fadd_rn(bcx, hw);
        p5[3] = __fadd_rn(bcy, hh);
        p5[4] = pro[((size_t)b * NN + idx) * NC + c];
    }
    if (maskMode == 1) {
        float* mb = out + (size_t)NB * NC * NN * 5 + (size_t)(b * NC + c) * NN;
        for (int t = tid; t < S; t += blockDim.x) mb[t] = 1.0f;
    } else if (maskMode == 2) {
        unsigned char* mb = (unsigned char*)(out + (size_t)NB * NC * NN * 5)
                          + (size_t)(b * NC + c) * NN;
        for (int t = tid; t < S; t += blockDim.x) mb[t] = 1;
    }
}

// ---------------------------------------------------------------------------
// Launch
// ---------------------------------------------------------------------------
extern "C" void kernel_launch(void* const* d_in, const int* in_sizes, int n_in,
                              void* d_out, int out_size) {
    const float* pro    = (const float*)d_in[0];  // (B,N,C)
    const float* con    = (const float*)d_in[1];  // (B,N,C)
    const float* boxes  = (const float*)d_in[2];  // (B,N,4)
    const float* scales = (const float*)d_in[3];  // (B,)
    const float* conf   = (const float*)d_in[4];  // (C,)
    float* out = (float*)d_out;

    cudaFuncSetAttribute(k_adj, cudaFuncAttributeMaxDynamicSharedMemorySize, K1_SMEM);

    long long T5 = (long long)NB * NC * NN * 5;   // 1,152,000
    long long TM = (long long)NB * NC * NN;       //   230,400
    int maskMode = 0;
    if ((long long)out_size >= T5 + TM) maskMode = 1;       // mask as float
    else if ((long long)out_size > T5)  maskMode = 2;       // mask as bytes

    k_adj<<<dim3(NXB, NB), K1_THR, K1_SMEM>>>(boxes, out, out_size);
    k_valid<<<(NB * NN * 32 + 255) / 256, 256>>>(pro, con, conf);
    k_nms<<<dim3(NC, NB), 512>>>(pro, boxes, scales, out, maskMode);
}